// round 9
// baseline (speedup 1.0000x reference)
#include <cuda_runtime.h>

// ---------------- problem constants ----------------
#define BATCH   4096
#define F_STN   20
#define F_DYN   10
#define MLEN    50
#define EDIM    16
#define F_ALL   30
#define NPAIR   435
#define D_IN    (NPAIR * EDIM)     // 6960
#define HID     512
#define BN_EPS  1e-5f

// ---------------- scratch (device globals; no allocs allowed) ----------------
__device__ __align__(16) float g_emb[BATCH * F_ALL * EDIM];       // 7.9 MB
__device__ float g_lr[BATCH];
__device__ __align__(16) float g_x[(size_t)BATCH * D_IN];         // 114 MB
__device__ float g_stat1[2 * D_IN];                               // col sum / sumsq of x
__device__ __align__(16) float g_W1s[D_IN * HID];                 // BN1-folded W1
__device__ float g_c1[HID];
__device__ __align__(16) float g_a1[BATCH * HID];                 // relu(h1)
__device__ float g_stat2[2 * HID];
__device__ __align__(16) float g_W2s[HID * HID];
__device__ float g_c2[HID];
__device__ __align__(16) float g_a2[BATCH * HID];                 // relu(h2)
__device__ float g_stat3[2 * HID];
__device__ float g_w3v[HID];                                      // s3 * rowsum(W3)
__device__ float g_k3;                                            // scalar const

// ---------------- kernel 0: zero the stat accumulators ----------------
__global__ void zero_stats_kernel()
{
    int i = blockIdx.x * blockDim.x + threadIdx.x;
    if (i < 2 * D_IN) g_stat1[i] = 0.f;
    if (i < 2 * HID) { g_stat2[i] = 0.f; g_stat3[i] = 0.f; }
}

// ---------------- kernel 1: embedding gather + masked mean + linear(lr) part --------
// grid = BATCH, block = 512
__global__ __launch_bounds__(512) void gather_kernel(
    const int*   __restrict__ static_ids,
    const int*   __restrict__ dyn_ids,
    const int*   __restrict__ dyn_len,
    const float* __restrict__ st_emb,
    const float* __restrict__ dy_emb,
    const float* __restrict__ st_lr,
    const float* __restrict__ dy_lr)
{
    int b = blockIdx.x;
    int tid = threadIdx.x;

    if (tid < F_STN * EDIM) {                       // static lookups: 320 threads
        int f = tid >> 4, e = tid & 15;
        int id = static_ids[b * F_STN + f];
        g_emb[(b * F_ALL + f) * EDIM + e] = st_emb[id * EDIM + e];
    } else if (tid < (F_STN + F_DYN) * EDIM) {      // dynamic masked mean: 160 threads
        int t = tid - F_STN * EDIM;
        int f = t >> 4, e = t & 15;
        int len = dyn_len[b * F_DYN + f]; if (len < 1) len = 1;
        const int* ids = dyn_ids + (b * F_DYN + f) * MLEN;
        float s = 0.f;
        int m = 0;
        for (; m + 4 <= len; m += 4) {              // MLP=4 over the gather
            int i0 = ids[m], i1 = ids[m + 1], i2 = ids[m + 2], i3 = ids[m + 3];
            s += dy_emb[i0 * EDIM + e];
            s += dy_emb[i1 * EDIM + e];
            s += dy_emb[i2 * EDIM + e];
            s += dy_emb[i3 * EDIM + e];
        }
        for (; m < len; ++m) s += dy_emb[ids[m] * EDIM + e];
        g_emb[(b * F_ALL + F_STN + f) * EDIM + e] = s / (float)len;
    } else {                                        // lr terms: last warp (32 threads)
        int lane = tid - (F_STN + F_DYN) * EDIM;    // 0..31
        float s = 0.f;
        if (lane < F_STN) s += st_lr[static_ids[b * F_STN + lane]];
        const int* ids = dyn_ids + b * F_DYN * MLEN;
        for (int f = 0; f < F_DYN; ++f) {
            int len = dyn_len[b * F_DYN + f]; if (len < 1) len = 1;
            if (lane < len)       s += dy_lr[ids[f * MLEN + lane]];
            if (lane + 32 < len)  s += dy_lr[ids[f * MLEN + lane + 32]];
        }
        for (int off = 16; off > 0; off >>= 1)
            s += __shfl_down_sync(0xffffffffu, s, off);
        if (lane == 0) g_lr[b] = s;
    }
}

// ---------------- kernel 2: pairwise products + BN1 batch stats ----------------
// block = 256 (16 pairs x 16 e), handles 16 batch rows; grid = (28 p-tiles, 256 b-tiles)
__global__ __launch_bounds__(256) void pairs_kernel()
{
    __shared__ float se[16 * F_ALL * EDIM];         // 16 rows x 480 floats = 30 KB
    int b0 = blockIdx.y * 16;
    int p0 = blockIdx.x * 16;
    int tid = threadIdx.x;

    const float4* src = (const float4*)(g_emb + (size_t)b0 * F_ALL * EDIM);
    float4* dst = (float4*)se;
    #pragma unroll 2
    for (int i = tid; i < 16 * F_ALL * EDIM / 4; i += 256) dst[i] = src[i];
    __syncthreads();

    int pl = tid >> 4, e = tid & 15;
    int p = p0 + pl;
    if (p < NPAIR) {
        // strict upper-tri row-major: (i,j), i<j
        int i = 0, rem = p;
        while (rem >= (F_ALL - 1 - i)) { rem -= (F_ALL - 1 - i); ++i; }
        int j = i + 1 + rem;
        int col = p * EDIM + e;
        int oi = i * EDIM + e, oj = j * EDIM + e;
        float sum = 0.f, sq = 0.f;
        #pragma unroll
        for (int r = 0; r < 16; ++r) {
            float v = se[r * F_ALL * EDIM + oi] * se[r * F_ALL * EDIM + oj];
            g_x[(size_t)(b0 + r) * D_IN + col] = v;
            sum += v; sq += v * v;
        }
        atomicAdd(&g_stat1[col], sum);
        atomicAdd(&g_stat1[D_IN + col], sq);
    }
}

// ---------------- BN folding: W' = s (.) W ; c = o @ W + b_lin ----------------
template <int LAYER>   // 1: D_IN->HID (stat1), 2: HID->HID (stat2)
__global__ void scale_w_kernel(const float* __restrict__ W,
                               const float* __restrict__ gamma)
{
    constexpr int ROWS = (LAYER == 1) ? D_IN : HID;
    const float* stats = (LAYER == 1) ? g_stat1 : g_stat2;
    float* Wo = (LAYER == 1) ? g_W1s : g_W2s;
    int idx = blockIdx.x * blockDim.x + threadIdx.x;
    if (idx >= ROWS * HID) return;
    int d = idx >> 9;
    float mean = stats[d] * (1.f / BATCH);
    float var  = stats[ROWS + d] * (1.f / BATCH) - mean * mean;
    float s = gamma[d] * rsqrtf(var + BN_EPS);
    Wo[idx] = W[idx] * s;
}

template <int LAYER>
__global__ __launch_bounds__(256) void cvec_kernel(const float* __restrict__ W,
                                                   const float* __restrict__ gamma,
                                                   const float* __restrict__ beta,
                                                   const float* __restrict__ blin)
{
    constexpr int ROWS = (LAYER == 1) ? D_IN : HID;
    const float* stats = (LAYER == 1) ? g_stat1 : g_stat2;
    float* cvec = (LAYER == 1) ? g_c1 : g_c2;
    __shared__ float red[8][32];
    int nl = threadIdx.x & 31;
    int dg = threadIdx.x >> 5;
    int n = blockIdx.x * 32 + nl;
    float acc = 0.f;
    for (int d = dg; d < ROWS; d += 8) {
        float mean = stats[d] * (1.f / BATCH);
        float var  = stats[ROWS + d] * (1.f / BATCH) - mean * mean;
        float s = gamma[d] * rsqrtf(var + BN_EPS);
        float o = beta[d] - mean * s;
        acc += o * W[d * HID + n];
    }
    red[dg][nl] = acc;
    __syncthreads();
    if (dg == 0) {
        float t = acc;
        #pragma unroll
        for (int g = 1; g < 8; ++g) t += red[g][nl];
        cvec[n] = t + blin[n];
    }
}

// ---------------- SGEMM + bias + relu + next-layer BN stats ----------------
// C[B x 512] = A[B x K] @ W'[K x 512] + c ; out = relu(C); atomics: colsum/colsumsq
// BM=BN=64, BK=16, 256 threads, 4x4 microtile, double-buffered smem
template <int LAYER>   // 1: A=g_x (K=D_IN) -> g_a1/stat2 ; 2: A=g_a1 (K=HID) -> g_a2/stat3
__global__ __launch_bounds__(256) void gemm_relu_stats_kernel()
{
    constexpr int K = (LAYER == 1) ? D_IN : HID;
    const float* A    = (LAYER == 1) ? g_x   : g_a1;
    const float* Bw   = (LAYER == 1) ? g_W1s : g_W2s;
    const float* cvec = (LAYER == 1) ? g_c1  : g_c2;
    float* Out        = (LAYER == 1) ? g_a1  : g_a2;
    float* stats      = (LAYER == 1) ? g_stat2 : g_stat3;

    __shared__ float As[2][16][64];
    __shared__ float Bs[2][16][64];
    __shared__ float s_sum[64], s_sq[64];

    int tid = threadIdx.x;
    int m0 = blockIdx.x * 64;
    int n0 = blockIdx.y * 64;
    if (tid < 64) { s_sum[tid] = 0.f; s_sq[tid] = 0.f; }

    int aRow = tid >> 2;            // 0..63
    int aK   = (tid & 3) * 4;       // 0,4,8,12
    int bK   = tid >> 4;            // 0..15
    int bN   = (tid & 15) * 4;      // 0..60

    const float* Aptr = A + (size_t)(m0 + aRow) * K + aK;
    const float* Bptr = Bw + (size_t)bK * HID + n0 + bN;

    {   // prologue: tile 0
        float4 av = *(const float4*)Aptr;
        float4 bv = *(const float4*)Bptr;
        As[0][aK + 0][aRow] = av.x; As[0][aK + 1][aRow] = av.y;
        As[0][aK + 2][aRow] = av.z; As[0][aK + 3][aRow] = av.w;
        *(float4*)&Bs[0][bK][bN] = bv;
    }
    __syncthreads();

    int tx = tid & 15, ty = tid >> 4;
    float acc[4][4];
    #pragma unroll
    for (int i = 0; i < 4; ++i)
        #pragma unroll
        for (int j = 0; j < 4; ++j) acc[i][j] = 0.f;

    constexpr int NT = K / 16;
    for (int t = 0; t < NT; ++t) {
        int cur = t & 1;
        float4 av, bv;
        if (t + 1 < NT) {
            av = *(const float4*)(Aptr + (t + 1) * 16);
            bv = *(const float4*)(Bptr + (size_t)(t + 1) * 16 * HID);
        }
        #pragma unroll
        for (int kk = 0; kk < 16; ++kk) {
            float4 a = *(const float4*)&As[cur][kk][ty * 4];
            float4 b = *(const float4*)&Bs[cur][kk][tx * 4];
            acc[0][0] += a.x * b.x; acc[0][1] += a.x * b.y; acc[0][2] += a.x * b.z; acc[0][3] += a.x * b.w;
            acc[1][0] += a.y * b.x; acc[1][1] += a.y * b.y; acc[1][2] += a.y * b.z; acc[1][3] += a.y * b.w;
            acc[2][0] += a.z * b.x; acc[2][1] += a.z * b.y; acc[2][2] += a.z * b.z; acc[2][3] += a.z * b.w;
            acc[3][0] += a.w * b.x; acc[3][1] += a.w * b.y; acc[3][2] += a.w * b.z; acc[3][3] += a.w * b.w;
        }
        if (t + 1 < NT) {
            int nxt = cur ^ 1;
            As[nxt][aK + 0][aRow] = av.x; As[nxt][aK + 1][aRow] = av.y;
            As[nxt][aK + 2][aRow] = av.z; As[nxt][aK + 3][aRow] = av.w;
            *(float4*)&Bs[nxt][bK][bN] = bv;
        }
        __syncthreads();
    }

    // epilogue: +bias, relu, store, per-column stats
    float cv[4];
    #pragma unroll
    for (int j = 0; j < 4; ++j) cv[j] = cvec[n0 + tx * 4 + j];
    float csum[4] = {0, 0, 0, 0}, csq[4] = {0, 0, 0, 0};
    #pragma unroll
    for (int i = 0; i < 4; ++i) {
        int row = m0 + ty * 4 + i;
        float v0 = fmaxf(acc[i][0] + cv[0], 0.f);
        float v1 = fmaxf(acc[i][1] + cv[1], 0.f);
        float v2 = fmaxf(acc[i][2] + cv[2], 0.f);
        float v3 = fmaxf(acc[i][3] + cv[3], 0.f);
        *(float4*)(Out + (size_t)row * HID + n0 + tx * 4) = make_float4(v0, v1, v2, v3);
        csum[0] += v0; csq[0] += v0 * v0;
        csum[1] += v1; csq[1] += v1 * v1;
        csum[2] += v2; csq[2] += v2 * v2;
        csum[3] += v3; csq[3] += v3 * v3;
    }
    #pragma unroll
    for (int j = 0; j < 4; ++j) {
        atomicAdd(&s_sum[tx * 4 + j], csum[j]);
        atomicAdd(&s_sq[tx * 4 + j],  csq[j]);
    }
    __syncthreads();
    if (tid < 64) {
        atomicAdd(&stats[n0 + tid], s_sum[tid]);
        atomicAdd(&stats[HID + n0 + tid], s_sq[tid]);
    }
}

// ---------------- layer-3 collapse: w3v = s3 * rowsum(W3), k3 = o3.rowsum + sum(b3) ----
__global__ __launch_bounds__(512) void prep3_kernel(const float* __restrict__ W3,
                                                    const float* __restrict__ gamma,
                                                    const float* __restrict__ beta,
                                                    const float* __restrict__ blin)
{
    __shared__ float red[512];
    int k = threadIdx.x;
    float R = 0.f;
    const float* row = W3 + (size_t)k * HID;
    #pragma unroll 8
    for (int n = 0; n < HID; ++n) R += row[n];
    float mean = g_stat3[k] * (1.f / BATCH);
    float var  = g_stat3[HID + k] * (1.f / BATCH) - mean * mean;
    float s = gamma[k] * rsqrtf(var + BN_EPS);
    float o = beta[k] - mean * s;
    g_w3v[k] = s * R;
    red[k] = o * R + blin[k];
    __syncthreads();
    for (int off = 256; off > 0; off >>= 1) {
        if (k < off) red[k] += red[k + off];
        __syncthreads();
    }
    if (k == 0) g_k3 = red[0];
}

// ---------------- final: score[b] = bias + lr[b] + k3 + a2[b,:].w3v ----------------
__global__ __launch_bounds__(256) void final_kernel(const float* __restrict__ bias,
                                                    float* __restrict__ out)
{
    __shared__ float sw[HID];
    int tid = threadIdx.x;
    sw[tid] = g_w3v[tid];
    sw[tid + 256] = g_w3v[tid + 256];
    __syncthreads();
    int warp = tid >> 5, lane = tid & 31;
    int b = blockIdx.x * 8 + warp;
    const float* arow = g_a2 + (size_t)b * HID;
    float s = 0.f;
    #pragma unroll
    for (int k = lane; k < HID; k += 32) s += arow[k] * sw[k];
    for (int off = 16; off > 0; off >>= 1)
        s += __shfl_down_sync(0xffffffffu, s, off);
    if (lane == 0) out[b] = bias[0] + g_lr[b] + g_k3 + s;
}

// ---------------- launch ----------------
extern "C" void kernel_launch(void* const* d_in, const int* in_sizes, int n_in,
                              void* d_out, int out_size)
{
    const int*   static_ids      = (const int*)  d_in[0];
    const int*   dynamic_ids     = (const int*)  d_in[1];
    const int*   dynamic_lengths = (const int*)  d_in[2];
    const float* st_emb = (const float*)d_in[3];
    const float* dy_emb = (const float*)d_in[4];
    const float* st_lr  = (const float*)d_in[5];
    const float* dy_lr  = (const float*)d_in[6];
    const float* bias   = (const float*)d_in[7];
    const float* bn1_g  = (const float*)d_in[8];
    const float* bn1_b  = (const float*)d_in[9];
    const float* W1     = (const float*)d_in[10];
    const float* b1     = (const float*)d_in[11];
    const float* bn2_g  = (const float*)d_in[12];
    const float* bn2_b  = (const float*)d_in[13];
    const float* W2     = (const float*)d_in[14];
    const float* b2     = (const float*)d_in[15];
    const float* bn3_g  = (const float*)d_in[16];
    const float* bn3_b  = (const float*)d_in[17];
    const float* W3     = (const float*)d_in[18];
    const float* b3     = (const float*)d_in[19];
    // inputs 20..23 (bn_out_*, W_out, b_out) feed a branch that never reaches the scores
    float* out = (float*)d_out;

    zero_stats_kernel<<<(2 * D_IN + 255) / 256, 256>>>();
    gather_kernel<<<BATCH, 512>>>(static_ids, dynamic_ids, dynamic_lengths,
                                  st_emb, dy_emb, st_lr, dy_lr);
    pairs_kernel<<<dim3((NPAIR + 15) / 16, BATCH / 16), 256>>>();

    scale_w_kernel<1><<<(D_IN * HID + 255) / 256, 256>>>(W1, bn1_g);
    cvec_kernel<1><<<16, 256>>>(W1, bn1_g, bn1_b, b1);
    gemm_relu_stats_kernel<1><<<dim3(BATCH / 64, HID / 64), 256>>>();

    scale_w_kernel<2><<<(HID * HID + 255) / 256, 256>>>(W2, bn2_g);
    cvec_kernel<2><<<16, 256>>>(W2, bn2_g, bn2_b, b2);
    gemm_relu_stats_kernel<2><<<dim3(BATCH / 64, HID / 64), 256>>>();

    prep3_kernel<<<1, 512>>>(W3, bn3_g, bn3_b, b3);
    final_kernel<<<BATCH / 8, 256>>>(bias, out);
}

// round 13
// speedup vs baseline: 1.4041x; 1.4041x over previous
#include <cuda_runtime.h>
#include <cstdint>

// ---------------- problem constants ----------------
#define BATCH   4096
#define F_STN   20
#define F_DYN   10
#define MLEN    50
#define EDIM    16
#define F_ALL   30
#define NPAIR   435
#define D_IN    (NPAIR * EDIM)     // 6960
#define HID     512
#define BN_EPS  1e-5f

// ---------------- scratch (device globals; no allocs allowed) ----------------
__device__ __align__(16) float g_emb[BATCH * F_ALL * EDIM];       // 7.9 MB
__device__ float g_lr[BATCH];
__device__ __align__(16) float g_x[(size_t)BATCH * D_IN];         // 114 MB
__device__ float g_stat1[2 * D_IN];                               // col sum / sumsq of x
__device__ __align__(16) float g_W1s[D_IN * HID];                 // BN1-folded W1
__device__ float g_c1[HID];
__device__ __align__(16) float g_a1[BATCH * HID];                 // relu(h1)
__device__ float g_stat2[2 * HID];
__device__ __align__(16) float g_W2s[HID * HID];
__device__ float g_c2[HID];
__device__ __align__(16) float g_a2[BATCH * HID];                 // relu(h2)
__device__ float g_stat3[2 * HID];
__device__ float g_w3v[HID];                                      // s3 * rowsum(W3)
__device__ float g_k3;                                            // scalar const

__device__ __forceinline__ float to_tf32(float x)
{
    float r;
    asm("cvt.rna.tf32.f32 %0, %1;" : "=f"(r) : "f"(x));
    return r;
}

// ---------------- kernel 0: zero the stat accumulators ----------------
__global__ void zero_stats_kernel()
{
    int i = blockIdx.x * blockDim.x + threadIdx.x;
    if (i < 2 * D_IN) g_stat1[i] = 0.f;
    if (i < 2 * HID) { g_stat2[i] = 0.f; g_stat3[i] = 0.f; }
}

// ---------------- kernel 1: embedding gather + masked mean + linear(lr) part --------
__global__ __launch_bounds__(512) void gather_kernel(
    const int*   __restrict__ static_ids,
    const int*   __restrict__ dyn_ids,
    const int*   __restrict__ dyn_len,
    const float* __restrict__ st_emb,
    const float* __restrict__ dy_emb,
    const float* __restrict__ st_lr,
    const float* __restrict__ dy_lr)
{
    int b = blockIdx.x;
    int tid = threadIdx.x;

    if (tid < F_STN * EDIM) {                       // static lookups: 320 threads
        int f = tid >> 4, e = tid & 15;
        int id = static_ids[b * F_STN + f];
        g_emb[(b * F_ALL + f) * EDIM + e] = st_emb[id * EDIM + e];
    } else if (tid < (F_STN + F_DYN) * EDIM) {      // dynamic masked mean: 160 threads
        int t = tid - F_STN * EDIM;
        int f = t >> 4, e = t & 15;
        int len = dyn_len[b * F_DYN + f]; if (len < 1) len = 1;
        const int* ids = dyn_ids + (b * F_DYN + f) * MLEN;
        float s = 0.f;
        int m = 0;
        for (; m + 4 <= len; m += 4) {
            int i0 = ids[m], i1 = ids[m + 1], i2 = ids[m + 2], i3 = ids[m + 3];
            s += dy_emb[i0 * EDIM + e];
            s += dy_emb[i1 * EDIM + e];
            s += dy_emb[i2 * EDIM + e];
            s += dy_emb[i3 * EDIM + e];
        }
        for (; m < len; ++m) s += dy_emb[ids[m] * EDIM + e];
        g_emb[(b * F_ALL + F_STN + f) * EDIM + e] = s / (float)len;
    } else {                                        // lr terms: last warp
        int lane = tid - (F_STN + F_DYN) * EDIM;
        float s = 0.f;
        if (lane < F_STN) s += st_lr[static_ids[b * F_STN + lane]];
        const int* ids = dyn_ids + b * F_DYN * MLEN;
        for (int f = 0; f < F_DYN; ++f) {
            int len = dyn_len[b * F_DYN + f]; if (len < 1) len = 1;
            if (lane < len)       s += dy_lr[ids[f * MLEN + lane]];
            if (lane + 32 < len)  s += dy_lr[ids[f * MLEN + lane + 32]];
        }
        for (int off = 16; off > 0; off >>= 1)
            s += __shfl_down_sync(0xffffffffu, s, off);
        if (lane == 0) g_lr[b] = s;
    }
}

// ---------------- kernel 2: pairwise products + BN1 batch stats ----------------
__global__ __launch_bounds__(256) void pairs_kernel()
{
    __shared__ float se[16 * F_ALL * EDIM];
    int b0 = blockIdx.y * 16;
    int p0 = blockIdx.x * 16;
    int tid = threadIdx.x;

    const float4* src = (const float4*)(g_emb + (size_t)b0 * F_ALL * EDIM);
    float4* dst = (float4*)se;
    #pragma unroll 2
    for (int i = tid; i < 16 * F_ALL * EDIM / 4; i += 256) dst[i] = src[i];
    __syncthreads();

    int pl = tid >> 4, e = tid & 15;
    int p = p0 + pl;
    if (p < NPAIR) {
        int i = 0, rem = p;
        while (rem >= (F_ALL - 1 - i)) { rem -= (F_ALL - 1 - i); ++i; }
        int j = i + 1 + rem;
        int col = p * EDIM + e;
        int oi = i * EDIM + e, oj = j * EDIM + e;
        float sum = 0.f, sq = 0.f;
        #pragma unroll
        for (int r = 0; r < 16; ++r) {
            float v = se[r * F_ALL * EDIM + oi] * se[r * F_ALL * EDIM + oj];
            g_x[(size_t)(b0 + r) * D_IN + col] = v;
            sum += v; sq += v * v;
        }
        atomicAdd(&g_stat1[col], sum);
        atomicAdd(&g_stat1[D_IN + col], sq);
    }
}

// ---------------- BN folding: W' = s (.) W (float4 vectorized) ----------------
template <int LAYER>
__global__ void scale_w_kernel(const float* __restrict__ W,
                               const float* __restrict__ gamma)
{
    constexpr int ROWS = (LAYER == 1) ? D_IN : HID;
    const float* stats = (LAYER == 1) ? g_stat1 : g_stat2;
    float* Wo = (LAYER == 1) ? g_W1s : g_W2s;
    int idx = blockIdx.x * blockDim.x + threadIdx.x;     // float4 index
    if (idx >= ROWS * HID / 4) return;
    int d = idx >> 7;                                    // (idx*4)/512
    float mean = stats[d] * (1.f / BATCH);
    float var  = stats[ROWS + d] * (1.f / BATCH) - mean * mean;
    float s = gamma[d] * rsqrtf(var + BN_EPS);
    float4 w = ((const float4*)W)[idx];
    w.x *= s; w.y *= s; w.z *= s; w.w *= s;
    ((float4*)Wo)[idx] = w;
}

template <int LAYER>
__global__ __launch_bounds__(256) void cvec_kernel(const float* __restrict__ W,
                                                   const float* __restrict__ gamma,
                                                   const float* __restrict__ beta,
                                                   const float* __restrict__ blin)
{
    constexpr int ROWS = (LAYER == 1) ? D_IN : HID;
    const float* stats = (LAYER == 1) ? g_stat1 : g_stat2;
    float* cvec = (LAYER == 1) ? g_c1 : g_c2;
    __shared__ float red[8][32];
    int nl = threadIdx.x & 31;
    int dg = threadIdx.x >> 5;
    int n = blockIdx.x * 32 + nl;
    float acc = 0.f;
    for (int d = dg; d < ROWS; d += 8) {
        float mean = stats[d] * (1.f / BATCH);
        float var  = stats[ROWS + d] * (1.f / BATCH) - mean * mean;
        float s = gamma[d] * rsqrtf(var + BN_EPS);
        float o = beta[d] - mean * s;
        acc += o * W[d * HID + n];
    }
    red[dg][nl] = acc;
    __syncthreads();
    if (dg == 0) {
        float t = acc;
        #pragma unroll
        for (int g = 1; g < 8; ++g) t += red[g][nl];
        cvec[n] = t + blin[n];
    }
}

// ============ GEMM1 in tf32 tensor cores (mma.sync m16n8k8) ============
// C[4096 x 512] = g_x[4096 x 6960] @ g_W1s[6960 x 512]; +c1, relu -> g_a1; stats -> g_stat2
// BM=128, BN=64, BK=16; 8 warps (4m x 2n), warp tile 32x32; double-buffered smem.
__global__ __launch_bounds__(256) void gemm1_tf32_kernel()
{
    constexpr int K = D_IN;
    constexpr int NT = K / 16;          // 435
    __shared__ float As[2][16][136];    // padded: bank-conflict-free frag reads
    __shared__ float Bs[2][16][72];
    __shared__ float s_sum[64], s_sq[64];

    int tid = threadIdx.x;
    int m0 = blockIdx.x * 128;
    int n0 = blockIdx.y * 64;
    if (tid < 64) { s_sum[tid] = 0.f; s_sq[tid] = 0.f; }

    int warp = tid >> 5, lane = tid & 31;
    int wm = (warp & 3) * 32;           // warp m offset within block
    int wn = (warp >> 2) * 32;          // warp n offset within block
    int gr = lane >> 2;                 // group row 0..7
    int gc = lane & 3;                  // group col 0..3

    // global-load assignments
    int aRow = tid & 127;               // 0..127
    int aK   = (tid >> 7) * 8;          // 0 or 8
    int bK   = tid >> 4;                // 0..15
    int bN   = (tid & 15) * 4;

    const float* Aptr = g_x + (size_t)(m0 + aRow) * K + aK;
    const float* Bptr = g_W1s + (size_t)bK * HID + n0 + bN;

    {   // prologue: tile 0
        float4 a0 = *(const float4*)Aptr;
        float4 a1 = *(const float4*)(Aptr + 4);
        float4 bv = *(const float4*)Bptr;
        As[0][aK + 0][aRow] = to_tf32(a0.x); As[0][aK + 1][aRow] = to_tf32(a0.y);
        As[0][aK + 2][aRow] = to_tf32(a0.z); As[0][aK + 3][aRow] = to_tf32(a0.w);
        As[0][aK + 4][aRow] = to_tf32(a1.x); As[0][aK + 5][aRow] = to_tf32(a1.y);
        As[0][aK + 6][aRow] = to_tf32(a1.z); As[0][aK + 7][aRow] = to_tf32(a1.w);
        Bs[0][bK][bN + 0] = to_tf32(bv.x); Bs[0][bK][bN + 1] = to_tf32(bv.y);
        Bs[0][bK][bN + 2] = to_tf32(bv.z); Bs[0][bK][bN + 3] = to_tf32(bv.w);
    }
    __syncthreads();

    float acc[2][4][4];
    #pragma unroll
    for (int mt = 0; mt < 2; ++mt)
        #pragma unroll
        for (int nt = 0; nt < 4; ++nt)
            #pragma unroll
            for (int r = 0; r < 4; ++r) acc[mt][nt][r] = 0.f;

    for (int t = 0; t < NT; ++t) {
        int cur = t & 1;
        float4 a0n, a1n, bvn;
        if (t + 1 < NT) {
            a0n = *(const float4*)(Aptr + (t + 1) * 16);
            a1n = *(const float4*)(Aptr + (t + 1) * 16 + 4);
            bvn = *(const float4*)(Bptr + (size_t)(t + 1) * 16 * HID);
        }
        #pragma unroll
        for (int ks = 0; ks < 16; ks += 8) {
            // A fragments for 2 m-tiles
            uint32_t af[2][4];
            #pragma unroll
            for (int mt = 0; mt < 2; ++mt) {
                int mb = wm + mt * 16;
                af[mt][0] = __float_as_uint(As[cur][ks + gc    ][mb + gr    ]);
                af[mt][1] = __float_as_uint(As[cur][ks + gc    ][mb + gr + 8]);
                af[mt][2] = __float_as_uint(As[cur][ks + gc + 4][mb + gr    ]);
                af[mt][3] = __float_as_uint(As[cur][ks + gc + 4][mb + gr + 8]);
            }
            // B fragments for 4 n-tiles
            uint32_t bf[4][2];
            #pragma unroll
            for (int nt = 0; nt < 4; ++nt) {
                int nb = wn + nt * 8;
                bf[nt][0] = __float_as_uint(Bs[cur][ks + gc    ][nb + gr]);
                bf[nt][1] = __float_as_uint(Bs[cur][ks + gc + 4][nb + gr]);
            }
            #pragma unroll
            for (int mt = 0; mt < 2; ++mt)
                #pragma unroll
                for (int nt = 0; nt < 4; ++nt) {
                    asm volatile(
                        "mma.sync.aligned.m16n8k8.row.col.f32.tf32.tf32.f32 "
                        "{%0,%1,%2,%3}, {%4,%5,%6,%7}, {%8,%9}, {%0,%1,%2,%3};"
                        : "+f"(acc[mt][nt][0]), "+f"(acc[mt][nt][1]),
                          "+f"(acc[mt][nt][2]), "+f"(acc[mt][nt][3])
                        : "r"(af[mt][0]), "r"(af[mt][1]), "r"(af[mt][2]), "r"(af[mt][3]),
                          "r"(bf[nt][0]), "r"(bf[nt][1]));
                }
        }
        if (t + 1 < NT) {
            int nxt = cur ^ 1;
            As[nxt][aK + 0][aRow] = to_tf32(a0n.x); As[nxt][aK + 1][aRow] = to_tf32(a0n.y);
            As[nxt][aK + 2][aRow] = to_tf32(a0n.z); As[nxt][aK + 3][aRow] = to_tf32(a0n.w);
            As[nxt][aK + 4][aRow] = to_tf32(a1n.x); As[nxt][aK + 5][aRow] = to_tf32(a1n.y);
            As[nxt][aK + 6][aRow] = to_tf32(a1n.z); As[nxt][aK + 7][aRow] = to_tf32(a1n.w);
            Bs[nxt][bK][bN + 0] = to_tf32(bvn.x); Bs[nxt][bK][bN + 1] = to_tf32(bvn.y);
            Bs[nxt][bK][bN + 2] = to_tf32(bvn.z); Bs[nxt][bK][bN + 3] = to_tf32(bvn.w);
        }
        __syncthreads();
    }

    // ---- epilogue: +bias, relu, store float2, column stats ----
    #pragma unroll
    for (int nt = 0; nt < 4; ++nt) {
        int cl = wn + nt * 8 + gc * 2;          // block-local column
        int cg = n0 + cl;                        // global column
        float cv0 = g_c1[cg], cv1 = g_c1[cg + 1];
        float s0 = 0.f, q0 = 0.f, s1 = 0.f, q1 = 0.f;
        #pragma unroll
        for (int mt = 0; mt < 2; ++mt) {
            int r0 = m0 + wm + mt * 16 + gr;
            float v0 = fmaxf(acc[mt][nt][0] + cv0, 0.f);
            float v1 = fmaxf(acc[mt][nt][1] + cv1, 0.f);
            float v2 = fmaxf(acc[mt][nt][2] + cv0, 0.f);
            float v3 = fmaxf(acc[mt][nt][3] + cv1, 0.f);
            *(float2*)(g_a1 + (size_t)r0 * HID + cg)       = make_float2(v0, v1);
            *(float2*)(g_a1 + (size_t)(r0 + 8) * HID + cg) = make_float2(v2, v3);
            s0 += v0 + v2; q0 += v0 * v0 + v2 * v2;
            s1 += v1 + v3; q1 += v1 * v1 + v3 * v3;
        }
        atomicAdd(&s_sum[cl], s0);     atomicAdd(&s_sq[cl], q0);
        atomicAdd(&s_sum[cl + 1], s1); atomicAdd(&s_sq[cl + 1], q1);
    }
    __syncthreads();
    if (tid < 64) {
        atomicAdd(&g_stat2[n0 + tid], s_sum[tid]);
        atomicAdd(&g_stat2[HID + n0 + tid], s_sq[tid]);
    }
}

// ---------------- fp32 SGEMM for layer 2 (K=512, small) ----------------
__global__ __launch_bounds__(256) void gemm2_relu_stats_kernel()
{
    constexpr int K = HID;
    const float* A    = g_a1;
    const float* Bw   = g_W2s;
    const float* cvec = g_c2;
    float* Out        = g_a2;
    float* stats      = g_stat3;

    __shared__ float As[2][16][64];
    __shared__ float Bs[2][16][64];
    __shared__ float s_sum[64], s_sq[64];

    int tid = threadIdx.x;
    int m0 = blockIdx.x * 64;
    int n0 = blockIdx.y * 64;
    if (tid < 64) { s_sum[tid] = 0.f; s_sq[tid] = 0.f; }

    int aRow = tid >> 2;
    int aK   = (tid & 3) * 4;
    int bK   = tid >> 4;
    int bN   = (tid & 15) * 4;

    const float* Aptr = A + (size_t)(m0 + aRow) * K + aK;
    const float* Bptr = Bw + (size_t)bK * HID + n0 + bN;

    {
        float4 av = *(const float4*)Aptr;
        float4 bv = *(const float4*)Bptr;
        As[0][aK + 0][aRow] = av.x; As[0][aK + 1][aRow] = av.y;
        As[0][aK + 2][aRow] = av.z; As[0][aK + 3][aRow] = av.w;
        *(float4*)&Bs[0][bK][bN] = bv;
    }
    __syncthreads();

    int tx = tid & 15, ty = tid >> 4;
    float acc[4][4];
    #pragma unroll
    for (int i = 0; i < 4; ++i)
        #pragma unroll
        for (int j = 0; j < 4; ++j) acc[i][j] = 0.f;

    constexpr int NT = K / 16;
    for (int t = 0; t < NT; ++t) {
        int cur = t & 1;
        float4 av, bv;
        if (t + 1 < NT) {
            av = *(const float4*)(Aptr + (t + 1) * 16);
            bv = *(const float4*)(Bptr + (size_t)(t + 1) * 16 * HID);
        }
        #pragma unroll
        for (int kk = 0; kk < 16; ++kk) {
            float4 a = *(const float4*)&As[cur][kk][ty * 4];
            float4 b = *(const float4*)&Bs[cur][kk][tx * 4];
            acc[0][0] += a.x * b.x; acc[0][1] += a.x * b.y; acc[0][2] += a.x * b.z; acc[0][3] += a.x * b.w;
            acc[1][0] += a.y * b.x; acc[1][1] += a.y * b.y; acc[1][2] += a.y * b.z; acc[1][3] += a.y * b.w;
            acc[2][0] += a.z * b.x; acc[2][1] += a.z * b.y; acc[2][2] += a.z * b.z; acc[2][3] += a.z * b.w;
            acc[3][0] += a.w * b.x; acc[3][1] += a.w * b.y; acc[3][2] += a.w * b.z; acc[3][3] += a.w * b.w;
        }
        if (t + 1 < NT) {
            int nxt = cur ^ 1;
            As[nxt][aK + 0][aRow] = av.x; As[nxt][aK + 1][aRow] = av.y;
            As[nxt][aK + 2][aRow] = av.z; As[nxt][aK + 3][aRow] = av.w;
            *(float4*)&Bs[nxt][bK][bN] = bv;
        }
        __syncthreads();
    }

    float cv[4];
    #pragma unroll
    for (int j = 0; j < 4; ++j) cv[j] = cvec[n0 + tx * 4 + j];
    float csum[4] = {0, 0, 0, 0}, csq[4] = {0, 0, 0, 0};
    #pragma unroll
    for (int i = 0; i < 4; ++i) {
        int row = m0 + ty * 4 + i;
        float v0 = fmaxf(acc[i][0] + cv[0], 0.f);
        float v1 = fmaxf(acc[i][1] + cv[1], 0.f);
        float v2 = fmaxf(acc[i][2] + cv[2], 0.f);
        float v3 = fmaxf(acc[i][3] + cv[3], 0.f);
        *(float4*)(Out + (size_t)row * HID + n0 + tx * 4) = make_float4(v0, v1, v2, v3);
        csum[0] += v0; csq[0] += v0 * v0;
        csum[1] += v1; csq[1] += v1 * v1;
        csum[2] += v2; csq[2] += v2 * v2;
        csum[3] += v3; csq[3] += v3 * v3;
    }
    #pragma unroll
    for (int j = 0; j < 4; ++j) {
        atomicAdd(&s_sum[tx * 4 + j], csum[j]);
        atomicAdd(&s_sq[tx * 4 + j],  csq[j]);
    }
    __syncthreads();
    if (tid < 64) {
        atomicAdd(&stats[n0 + tid], s_sum[tid]);
        atomicAdd(&stats[HID + n0 + tid], s_sq[tid]);
    }
}

// ---------------- layer-3 collapse ----------------
__global__ __launch_bounds__(512) void prep3_kernel(const float* __restrict__ W3,
                                                    const float* __restrict__ gamma,
                                                    const float* __restrict__ beta,
                                                    const float* __restrict__ blin)
{
    __shared__ float red[512];
    int k = threadIdx.x;
    float R = 0.f;
    const float* row = W3 + (size_t)k * HID;
    #pragma unroll 8
    for (int n = 0; n < HID; ++n) R += row[n];
    float mean = g_stat3[k] * (1.f / BATCH);
    float var  = g_stat3[HID + k] * (1.f / BATCH) - mean * mean;
    float s = gamma[k] * rsqrtf(var + BN_EPS);
    float o = beta[k] - mean * s;
    g_w3v[k] = s * R;
    red[k] = o * R + blin[k];
    __syncthreads();
    for (int off = 256; off > 0; off >>= 1) {
        if (k < off) red[k] += red[k + off];
        __syncthreads();
    }
    if (k == 0) g_k3 = red[0];
}

// ---------------- final scores ----------------
__global__ __launch_bounds__(256) void final_kernel(const float* __restrict__ bias,
                                                    float* __restrict__ out)
{
    __shared__ float sw[HID];
    int tid = threadIdx.x;
    sw[tid] = g_w3v[tid];
    sw[tid + 256] = g_w3v[tid + 256];
    __syncthreads();
    int warp = tid >> 5, lane = tid & 31;
    int b = blockIdx.x * 8 + warp;
    const float* arow = g_a2 + (size_t)b * HID;
    float s = 0.f;
    #pragma unroll
    for (int k = lane; k < HID; k += 32) s += arow[k] * sw[k];
    for (int off = 16; off > 0; off >>= 1)
        s += __shfl_down_sync(0xffffffffu, s, off);
    if (lane == 0) out[b] = bias[0] + g_lr[b] + g_k3 + s;
}

// ---------------- launch ----------------
extern "C" void kernel_launch(void* const* d_in, const int* in_sizes, int n_in,
                              void* d_out, int out_size)
{
    const int*   static_ids      = (const int*)  d_in[0];
    const int*   dynamic_ids     = (const int*)  d_in[1];
    const int*   dynamic_lengths = (const int*)  d_in[2];
    const float* st_emb = (const float*)d_in[3];
    const float* dy_emb = (const float*)d_in[4];
    const float* st_lr  = (const float*)d_in[5];
    const float* dy_lr  = (const float*)d_in[6];
    const float* bias   = (const float*)d_in[7];
    const float* bn1_g  = (const float*)d_in[8];
    const float* bn1_b  = (const float*)d_in[9];
    const float* W1     = (const float*)d_in[10];
    const float* b1     = (const float*)d_in[11];
    const float* bn2_g  = (const float*)d_in[12];
    const float* bn2_b  = (const float*)d_in[13];
    const float* W2     = (const float*)d_in[14];
    const float* b2     = (const float*)d_in[15];
    const float* bn3_g  = (const float*)d_in[16];
    const float* bn3_b  = (const float*)d_in[17];
    const float* W3     = (const float*)d_in[18];
    const float* b3     = (const float*)d_in[19];
    float* out = (float*)d_out;

    zero_stats_kernel<<<(2 * D_IN + 255) / 256, 256>>>();
    gather_kernel<<<BATCH, 512>>>(static_ids, dynamic_ids, dynamic_lengths,
                                  st_emb, dy_emb, st_lr, dy_lr);
    pairs_kernel<<<dim3((NPAIR + 15) / 16, BATCH / 16), 256>>>();

    scale_w_kernel<1><<<(D_IN * HID / 4 + 255) / 256, 256>>>(W1, bn1_g);
    cvec_kernel<1><<<16, 256>>>(W1, bn1_g, bn1_b, b1);
    gemm1_tf32_kernel<<<dim3(BATCH / 128, HID / 64), 256>>>();

    scale_w_kernel<2><<<(HID * HID / 4 + 255) / 256, 256>>>(W2, bn2_g);
    cvec_kernel<2><<<16, 256>>>(W2, bn2_g, bn2_b, b2);
    gemm2_relu_stats_kernel<<<dim3(BATCH / 64, HID / 64), 256>>>();

    prep3_kernel<<<1, 512>>>(W3, bn3_g, bn3_b, b3);
    final_kernel<<<BATCH / 8, 256>>>(bias, out);
}